// round 1
// baseline (speedup 1.0000x reference)
#include <cuda_runtime.h>
#include <math.h>

// GRU-style decoder cell:
//   r = sigmoid(x@Wr^T + hprev@Ur^T + c@Cr^T + br)
//   z = sigmoid(x@Wz^T + hprev@Uz^T + c@Cz^T + bz)
//   h = tanh   (x@Wh^T + (r*hprev)@Uh^T + c@Ch^T + bh)
//   out = z*h + (1-z)*hprev
//
// B=8192, IN=1024, H=1024, c: [B, 2048]
// Inputs (metadata order):
//  0:x 1:hprev 2:c 3:Wh 4:Wz 5:Wr 6:Uh 7:Uz 8:Ur 9:Ch 10:Cz 11:Cr 12:bh 13:bz 14:br

#define BATCH 8192
#define HID   1024

#define BM 128
#define BN 128
#define BK 16
#define TM 8
#define TN 8
// 256 threads: 16 (N) x 16 (M) micro-tile grid

// Scratch (allocation-free rule: __device__ globals)
__device__ float g_rh[(size_t)BATCH * HID];  // r * hprev
__device__ float g_z [(size_t)BATCH * HID];  // z

__global__ __launch_bounds__(256, 2)
void gate_gemm_kernel(
    const float* __restrict__ x,     // [B,1024]
    const float* __restrict__ A1,    // [B,1024] (hprev or rh)
    const float* __restrict__ c,     // [B,2048]
    const float* __restrict__ W0,    // [1024,1024]
    const float* __restrict__ W1,    // [1024,1024]
    const float* __restrict__ W2,    // [1024,2048]
    const float* __restrict__ bias,  // [1024]
    const float* __restrict__ hprev, // [B,1024] (epilogue)
    float* __restrict__ out,         // [B,1024]
    int mode)                        // 0: rh=sigmoid()*hprev, 1: z=sigmoid(), 2: final
{
    __shared__ float As[BK][BM];
    __shared__ float Ws[BK][BN];

    const int tid = threadIdx.x;
    const int tx  = tid & 15;   // N direction
    const int ty  = tid >> 4;   // M direction
    const int bm  = blockIdx.y * BM;
    const int bn  = blockIdx.x * BN;

    float acc[TM][TN];
#pragma unroll
    for (int i = 0; i < TM; ++i)
#pragma unroll
        for (int j = 0; j < TN; ++j)
            acc[i][j] = 0.0f;

    // K layout: [0,1024) -> x/W0, [1024,2048) -> A1/W1, [2048,4096) -> c/W2
    const int NUM_KT = 4096 / BK;  // 256 tiles
    for (int kt = 0; kt < NUM_KT; ++kt) {
        const float* Aseg;
        const float* Wseg;
        int ld, k0;
        if (kt < 64)       { Aseg = x;  Wseg = W0; ld = 1024; k0 = kt << 4; }
        else if (kt < 128) { Aseg = A1; Wseg = W1; ld = 1024; k0 = (kt - 64) << 4; }
        else               { Aseg = c;  Wseg = W2; ld = 2048; k0 = (kt - 128) << 4; }

        // Load 128x16 A-tile and 128x16 W-tile, transposed into smem.
        // 512 float4 slots each; 256 threads x 2.
#pragma unroll
        for (int i = 0; i < 2; ++i) {
            const int s   = tid + i * 256;
            const int row = s >> 2;          // 0..127
            const int cg  = (s & 3) << 2;    // 0,4,8,12
            const float4 va = *(const float4*)(Aseg + (size_t)(bm + row) * ld + k0 + cg);
            As[cg + 0][row] = va.x;
            As[cg + 1][row] = va.y;
            As[cg + 2][row] = va.z;
            As[cg + 3][row] = va.w;
            const float4 vw = *(const float4*)(Wseg + (size_t)(bn + row) * ld + k0 + cg);
            Ws[cg + 0][row] = vw.x;
            Ws[cg + 1][row] = vw.y;
            Ws[cg + 2][row] = vw.z;
            Ws[cg + 3][row] = vw.w;
        }
        __syncthreads();

#pragma unroll
        for (int k = 0; k < BK; ++k) {
            float a[TM], b[TN];
            float4 a0 = *(const float4*)&As[k][ty * TM];
            float4 a1 = *(const float4*)&As[k][ty * TM + 4];
            float4 b0 = *(const float4*)&Ws[k][tx * TN];
            float4 b1 = *(const float4*)&Ws[k][tx * TN + 4];
            a[0] = a0.x; a[1] = a0.y; a[2] = a0.z; a[3] = a0.w;
            a[4] = a1.x; a[5] = a1.y; a[6] = a1.z; a[7] = a1.w;
            b[0] = b0.x; b[1] = b0.y; b[2] = b0.z; b[3] = b0.w;
            b[4] = b1.x; b[5] = b1.y; b[6] = b1.z; b[7] = b1.w;
#pragma unroll
            for (int i = 0; i < TM; ++i)
#pragma unroll
                for (int j = 0; j < TN; ++j)
                    acc[i][j] = fmaf(a[i], b[j], acc[i][j]);
        }
        __syncthreads();
    }

    // Epilogue
#pragma unroll
    for (int i = 0; i < TM; ++i) {
        const int m = bm + ty * TM + i;
#pragma unroll
        for (int j = 0; j < TN; ++j) {
            const int n = bn + tx * TN + j;
            const size_t idx = (size_t)m * HID + n;
            float v = acc[i][j] + bias[n];
            if (mode == 0) {
                float r = 1.0f / (1.0f + expf(-v));
                out[idx] = r * hprev[idx];
            } else if (mode == 1) {
                out[idx] = 1.0f / (1.0f + expf(-v));
            } else {
                float hp = tanhf(v);
                float z  = g_z[idx];
                float h0 = hprev[idx];
                out[idx] = z * hp + (1.0f - z) * h0;
            }
        }
    }
}

extern "C" void kernel_launch(void* const* d_in, const int* in_sizes, int n_in,
                              void* d_out, int out_size)
{
    const float* x     = (const float*)d_in[0];
    const float* hprev = (const float*)d_in[1];
    const float* c     = (const float*)d_in[2];
    const float* Wh    = (const float*)d_in[3];
    const float* Wz    = (const float*)d_in[4];
    const float* Wr    = (const float*)d_in[5];
    const float* Uh    = (const float*)d_in[6];
    const float* Uz    = (const float*)d_in[7];
    const float* Ur    = (const float*)d_in[8];
    const float* Ch    = (const float*)d_in[9];
    const float* Cz    = (const float*)d_in[10];
    const float* Cr    = (const float*)d_in[11];
    const float* bh    = (const float*)d_in[12];
    const float* bz    = (const float*)d_in[13];
    const float* br    = (const float*)d_in[14];
    float* out = (float*)d_out;

    float* rh_ptr = nullptr;
    float* z_ptr  = nullptr;
    cudaGetSymbolAddress((void**)&rh_ptr, g_rh);
    cudaGetSymbolAddress((void**)&z_ptr,  g_z);

    dim3 grid(HID / BN, BATCH / BM);  // (8, 64)
    dim3 block(256);

    // r gate -> rh = sigmoid(pre_r) * hprev
    gate_gemm_kernel<<<grid, block>>>(x, hprev, c, Wr, Ur, Cr, br, hprev, rh_ptr, 0);
    // z gate -> z = sigmoid(pre_z)
    gate_gemm_kernel<<<grid, block>>>(x, hprev, c, Wz, Uz, Cz, bz, hprev, z_ptr, 1);
    // h gate (A1 = rh) -> out = z*tanh(pre_h) + (1-z)*hprev
    gate_gemm_kernel<<<grid, block>>>(x, rh_ptr, c, Wh, Uh, Ch, bh, hprev, out, 2);
}

// round 3
// speedup vs baseline: 3.4102x; 3.4102x over previous
#include <cuda_runtime.h>
#include <cstdint>
#include <math.h>

// GRU-style decoder cell via mma.sync tf32 (HMMA path; tcgen05 unavailable at compute_103).
//   r = sigmoid(x@Wr^T + hprev@Ur^T + c@Cr^T + br)   -> g_rh = r*hprev
//   z = sigmoid(x@Wz^T + hprev@Uz^T + c@Cz^T + bz)   -> g_z
//   h = tanh   (x@Wh^T + g_rh@Uh^T  + c@Ch^T + bh)   -> out = z*h + (1-z)*hprev
// B=8192, IN=1024, H=1024, c:[B,2048]; effective K=4096 per gate.

#define BATCH 8192
#define HID   1024
#define BM 256
#define BN 128
#define BK 32
#define BKP 36            // padded K stride (floats): bank = (4*row + k) % 32 -> conflict-free frags
#define STAGES 4
#define NCHUNK 128        // 4096 / 32

#define A_TILE (BM * BKP) // floats per A stage
#define B_TILE (BN * BKP)
#define SMEM_FLOATS (STAGES * (A_TILE + B_TILE))
#define SMEM_BYTES  (SMEM_FLOATS * 4)   // 4 * (9216+4608)*4 = 221184

// scratch (allocation-free rule)
__device__ float g_rh[(size_t)BATCH * HID];
__device__ float g_z [(size_t)BATCH * HID];

__device__ __forceinline__ void cp16(void* dst_smem, const void* src) {
    uint32_t d = (uint32_t)__cvta_generic_to_shared(dst_smem);
    asm volatile("cp.async.cg.shared.global [%0], [%1], 16;" :: "r"(d), "l"(src));
}
__device__ __forceinline__ void cp_commit() {
    asm volatile("cp.async.commit_group;" ::: "memory");
}
__device__ __forceinline__ void cp_wait3() {
    asm volatile("cp.async.wait_group 3;" ::: "memory");
}
__device__ __forceinline__ uint32_t f2tf32(float x) {
    uint32_t u;
    asm("cvt.rna.tf32.f32 %0, %1;" : "=r"(u) : "f"(x));
    return u;
}
__device__ __forceinline__ void mma_tf32(float* c, const uint32_t* a, const uint32_t* b) {
    asm volatile(
        "mma.sync.aligned.m16n8k8.row.col.f32.tf32.tf32.f32 "
        "{%0,%1,%2,%3}, {%4,%5,%6,%7}, {%8,%9}, {%0,%1,%2,%3};"
        : "+f"(c[0]), "+f"(c[1]), "+f"(c[2]), "+f"(c[3])
        : "r"(a[0]), "r"(a[1]), "r"(a[2]), "r"(a[3]), "r"(b[0]), "r"(b[1]));
}

__device__ __forceinline__ float fsigmoid(float v) { return 1.0f / (1.0f + __expf(-v)); }
__device__ __forceinline__ float ftanh(float v) {
    float e = __expf(-2.0f * v);
    return 2.0f / (1.0f + e) - 1.0f;
}

__global__ __launch_bounds__(512, 1)
void gate_mma_kernel(
    const float* __restrict__ x,     // [B,1024]
    const float* __restrict__ A1,    // [B,1024] (hprev or g_rh)
    const float* __restrict__ c,     // [B,2048]
    const float* __restrict__ W0,    // [1024,1024]
    const float* __restrict__ W1,    // [1024,1024]
    const float* __restrict__ W2,    // [1024,2048]
    const float* __restrict__ bias,  // [1024]
    const float* __restrict__ hprev, // [B,1024]
    const float* __restrict__ zbuf,  // [B,1024] (mode 2)
    float* __restrict__ out,         // [B,1024]
    int mode)                        // 0: rh, 1: z, 2: final
{
    extern __shared__ float sm[];
    float* As = sm;                       // [STAGES][BM][BKP]
    float* Bs = sm + STAGES * A_TILE;     // [STAGES][BN][BKP]

    const int tid  = threadIdx.x;
    const int lane = tid & 31;
    const int wid  = tid >> 5;
    const int g    = lane >> 2;   // 0..7
    const int tg   = lane & 3;    // 0..3
    const int wm   = wid >> 2;    // 0..3 -> 64-row slab
    const int wn   = wid & 3;     // 0..3 -> 32-col slab

    const int bm = blockIdx.y * BM;
    const int bn = blockIdx.x * BN;

    float acc[4][4][4];
#pragma unroll
    for (int i = 0; i < 4; ++i)
#pragma unroll
        for (int j = 0; j < 4; ++j)
#pragma unroll
            for (int k = 0; k < 4; ++k)
                acc[i][j][k] = 0.0f;

    // ---- async tile loader ----
    auto issue = [&](int i, int s) {
        const float* Aseg;
        const float* Wseg;
        int ld, k0;
        if (i < 32)      { Aseg = x;  Wseg = W0; ld = 1024; k0 = i * BK; }
        else if (i < 64) { Aseg = A1; Wseg = W1; ld = 1024; k0 = (i - 32) * BK; }
        else             { Aseg = c;  Wseg = W2; ld = 2048; k0 = (i - 64) * BK; }

        float* ad = As + s * A_TILE;
        float* bd = Bs + s * B_TILE;
        // A: 256 rows x 8 chunks(16B) = 2048; 512 threads -> 4 each
#pragma unroll
        for (int j = 0; j < 4; ++j) {
            const int idx = tid + j * 512;
            const int row = idx >> 3;
            const int ch  = (idx & 7) << 2;
            cp16(ad + row * BKP + ch, Aseg + (size_t)(bm + row) * ld + k0 + ch);
        }
        // B: 128 rows x 8 chunks = 1024; 512 threads -> 2 each
#pragma unroll
        for (int j = 0; j < 2; ++j) {
            const int idx = tid + j * 512;
            const int row = idx >> 3;
            const int ch  = (idx & 7) << 2;
            cp16(bd + row * BKP + ch, Wseg + (size_t)(bn + row) * ld + k0 + ch);
        }
        cp_commit();
    };

#pragma unroll
    for (int s = 0; s < STAGES; ++s) issue(s, s);

    int buf = 0;
    for (int i = 0; i < NCHUNK; ++i) {
        cp_wait3();
        __syncthreads();

        const float* A0 = As + buf * A_TILE + (wm * 64) * BKP;
        const float* B0 = Bs + buf * B_TILE + (wn * 32) * BKP;

#pragma unroll
        for (int ks = 0; ks < 4; ++ks) {
            const int kk = ks * 8;
            uint32_t a[4][4], b[4][2];
#pragma unroll
            for (int mf = 0; mf < 4; ++mf) {
                const float* ap = A0 + (mf * 16 + g) * BKP + kk + tg;
                a[mf][0] = f2tf32(ap[0]);
                a[mf][1] = f2tf32(ap[8 * BKP]);
                a[mf][2] = f2tf32(ap[4]);
                a[mf][3] = f2tf32(ap[8 * BKP + 4]);
            }
#pragma unroll
            for (int nf = 0; nf < 4; ++nf) {
                const float* bp = B0 + (nf * 8 + g) * BKP + kk + tg;
                b[nf][0] = f2tf32(bp[0]);
                b[nf][1] = f2tf32(bp[4]);
            }
#pragma unroll
            for (int mf = 0; mf < 4; ++mf)
#pragma unroll
                for (int nf = 0; nf < 4; ++nf)
                    mma_tf32(acc[mf][nf], a[mf], b[nf]);
        }

        __syncthreads();
        if (i + STAGES < NCHUNK) issue(i + STAGES, buf);
        buf = (buf == STAGES - 1) ? 0 : buf + 1;
    }

    // ---- epilogue ----
#pragma unroll
    for (int mf = 0; mf < 4; ++mf) {
#pragma unroll
        for (int nf = 0; nf < 4; ++nf) {
            const int n = bn + wn * 32 + nf * 8 + 2 * tg;
            const float2 bi = *(const float2*)(bias + n);
#pragma unroll
            for (int half = 0; half < 2; ++half) {
                const int m = bm + wm * 64 + mf * 16 + g + half * 8;
                const size_t idx = (size_t)m * HID + n;
                float v0 = acc[mf][nf][2 * half + 0] + bi.x;
                float v1 = acc[mf][nf][2 * half + 1] + bi.y;
                float2 o;
                if (mode == 0) {
                    const float2 hp = *(const float2*)(hprev + idx);
                    o.x = fsigmoid(v0) * hp.x;
                    o.y = fsigmoid(v1) * hp.y;
                } else if (mode == 1) {
                    o.x = fsigmoid(v0);
                    o.y = fsigmoid(v1);
                } else {
                    const float2 hp = *(const float2*)(hprev + idx);
                    const float2 zz = *(const float2*)(zbuf + idx);
                    o.x = fmaf(zz.x, ftanh(v0) - hp.x, hp.x);
                    o.y = fmaf(zz.y, ftanh(v1) - hp.y, hp.y);
                }
                *(float2*)(out + idx) = o;
            }
        }
    }
}

extern "C" void kernel_launch(void* const* d_in, const int* in_sizes, int n_in,
                              void* d_out, int out_size)
{
    const float* x     = (const float*)d_in[0];
    const float* hprev = (const float*)d_in[1];
    const float* c     = (const float*)d_in[2];
    const float* Wh    = (const float*)d_in[3];
    const float* Wz    = (const float*)d_in[4];
    const float* Wr    = (const float*)d_in[5];
    const float* Uh    = (const float*)d_in[6];
    const float* Uz    = (const float*)d_in[7];
    const float* Ur    = (const float*)d_in[8];
    const float* Ch    = (const float*)d_in[9];
    const float* Cz    = (const float*)d_in[10];
    const float* Cr    = (const float*)d_in[11];
    const float* bh    = (const float*)d_in[12];
    const float* bz    = (const float*)d_in[13];
    const float* br    = (const float*)d_in[14];
    float* out = (float*)d_out;

    float* rh_ptr = nullptr;
    float* z_ptr  = nullptr;
    cudaGetSymbolAddress((void**)&rh_ptr, g_rh);
    cudaGetSymbolAddress((void**)&z_ptr,  g_z);

    cudaFuncSetAttribute(gate_mma_kernel,
                         cudaFuncAttributeMaxDynamicSharedMemorySize, SMEM_BYTES);

    const dim3 grid(HID / BN, BATCH / BM);  // (8, 32)
    const dim3 block(512);

    // r gate -> g_rh = sigmoid(.) * hprev
    gate_mma_kernel<<<grid, block, SMEM_BYTES>>>(
        x, hprev, c, Wr, Ur, Cr, br, hprev, nullptr, rh_ptr, 0);
    // z gate -> g_z = sigmoid(.)
    gate_mma_kernel<<<grid, block, SMEM_BYTES>>>(
        x, hprev, c, Wz, Uz, Cz, bz, hprev, nullptr, z_ptr, 1);
    // h gate -> out = z*tanh(.) + (1-z)*hprev
    gate_mma_kernel<<<grid, block, SMEM_BYTES>>>(
        x, rh_ptr, c, Wh, Uh, Ch, bh, hprev, z_ptr, out, 2);
}

// round 4
// speedup vs baseline: 3.4738x; 1.0187x over previous
#include <cuda_runtime.h>
#include <cstdint>
#include <math.h>

// GRU-style decoder cell via mma.sync tf32 with hoisted tf32 rounding.
//   r = sigmoid(x@Wr^T + hprev@Ur^T + c@Cr^T + br)   -> g_rh = tf32(r*hprev)
//   z = sigmoid(x@Wz^T + hprev@Uz^T + c@Cz^T + bz)   -> g_z
//   h = tanh   (x@Wh^T + g_rh@Uh^T  + c@Ch^T + bh)   -> out = z*h + (1-z)*hprev
// B=8192, IN=1024, H=1024, c:[B,2048]; effective K=4096 per gate.

#define BATCH 8192
#define HID   1024
#define BM 256
#define BN 128
#define BK 32
#define BKP 36            // padded K stride (floats)
#define STAGES 4
#define NCHUNK 128        // 4096 / 32

#define A_TILE (BM * BKP)
#define B_TILE (BN * BKP)
#define SMEM_BYTES  (STAGES * (A_TILE + B_TILE) * 4)   // 221184

// ---- scratch (allocation-free rule: __device__ globals) ----
__device__ float g_rh[(size_t)BATCH * HID];     // tf32-rounded r*hprev
__device__ float g_z [(size_t)BATCH * HID];     // z
__device__ float g_xr[(size_t)BATCH * 1024];    // tf32(x)
__device__ float g_hr[(size_t)BATCH * 1024];    // tf32(hprev)
__device__ float g_cr[(size_t)BATCH * 2048];    // tf32(c)
// per gate: W (1M) | U (1M) | C (2M)  at gate*4M
__device__ float g_wts[(size_t)3 * 4 * 1024 * 1024];

__device__ __forceinline__ void cp16(void* dst_smem, const void* src) {
    uint32_t d = (uint32_t)__cvta_generic_to_shared(dst_smem);
    asm volatile("cp.async.cg.shared.global [%0], [%1], 16;" :: "r"(d), "l"(src));
}
__device__ __forceinline__ void cp_commit() {
    asm volatile("cp.async.commit_group;" ::: "memory");
}
__device__ __forceinline__ void cp_wait3() {
    asm volatile("cp.async.wait_group 3;" ::: "memory");
}
__device__ __forceinline__ uint32_t f2tf32(float x) {
    uint32_t u;
    asm("cvt.rna.tf32.f32 %0, %1;" : "=r"(u) : "f"(x));
    return u;
}
__device__ __forceinline__ void mma_tf32(float* c, const uint32_t* a, const uint32_t* b) {
    asm volatile(
        "mma.sync.aligned.m16n8k8.row.col.f32.tf32.tf32.f32 "
        "{%0,%1,%2,%3}, {%4,%5,%6,%7}, {%8,%9}, {%0,%1,%2,%3};"
        : "+f"(c[0]), "+f"(c[1]), "+f"(c[2]), "+f"(c[3])
        : "r"(a[0]), "r"(a[1]), "r"(a[2]), "r"(a[3]), "r"(b[0]), "r"(b[1]));
}

__device__ __forceinline__ float fsigmoid(float v) { return 1.0f / (1.0f + __expf(-v)); }
__device__ __forceinline__ float ftanh(float v) {
    float e = __expf(-2.0f * v);
    return 2.0f / (1.0f + e) - 1.0f;
}

// ---- pre-pass: tf32-round src into dst (vectorized) ----
__global__ __launch_bounds__(256)
void round_tf32_kernel(const float4* __restrict__ src, float4* __restrict__ dst, int n4)
{
    const int stride = gridDim.x * blockDim.x;
    for (int i = blockIdx.x * blockDim.x + threadIdx.x; i < n4; i += stride) {
        float4 v = src[i];
        v.x = __uint_as_float(f2tf32(v.x));
        v.y = __uint_as_float(f2tf32(v.y));
        v.z = __uint_as_float(f2tf32(v.z));
        v.w = __uint_as_float(f2tf32(v.w));
        dst[i] = v;
    }
}

__global__ __launch_bounds__(512, 1)
void gate_mma_kernel(
    const float* __restrict__ x,     // tf32 [B,1024]
    const float* __restrict__ A1,    // tf32 [B,1024] (g_hr or g_rh)
    const float* __restrict__ c,     // tf32 [B,2048]
    const float* __restrict__ W0,    // tf32 [1024,1024]
    const float* __restrict__ W1,    // tf32 [1024,1024]
    const float* __restrict__ W2,    // tf32 [1024,2048]
    const float* __restrict__ bias,
    const float* __restrict__ hprev, // fp32 (epilogue)
    const float* __restrict__ zbuf,  // (mode 2)
    float* __restrict__ out,
    int mode)
{
    extern __shared__ float sm[];
    float* As = sm;
    float* Bs = sm + STAGES * A_TILE;

    const int tid  = threadIdx.x;
    const int lane = tid & 31;
    const int wid  = tid >> 5;
    const int g    = lane >> 2;
    const int tg   = lane & 3;
    const int wm   = wid >> 2;
    const int wn   = wid & 3;

    const int bm = blockIdx.y * BM;
    const int bn = blockIdx.x * BN;

    float acc[4][4][4];
#pragma unroll
    for (int i = 0; i < 4; ++i)
#pragma unroll
        for (int j = 0; j < 4; ++j)
#pragma unroll
            for (int k = 0; k < 4; ++k)
                acc[i][j][k] = 0.0f;

    auto issue = [&](int i, int s) {
        const float* Aseg;
        const float* Wseg;
        int ld, k0;
        if (i < 32)      { Aseg = x;  Wseg = W0; ld = 1024; k0 = i * BK; }
        else if (i < 64) { Aseg = A1; Wseg = W1; ld = 1024; k0 = (i - 32) * BK; }
        else             { Aseg = c;  Wseg = W2; ld = 2048; k0 = (i - 64) * BK; }

        float* ad = As + s * A_TILE;
        float* bd = Bs + s * B_TILE;
#pragma unroll
        for (int j = 0; j < 4; ++j) {
            const int idx = tid + j * 512;
            const int row = idx >> 3;
            const int ch  = (idx & 7) << 2;
            cp16(ad + row * BKP + ch, Aseg + (size_t)(bm + row) * ld + k0 + ch);
        }
#pragma unroll
        for (int j = 0; j < 2; ++j) {
            const int idx = tid + j * 512;
            const int row = idx >> 3;
            const int ch  = (idx & 7) << 2;
            cp16(bd + row * BKP + ch, Wseg + (size_t)(bn + row) * ld + k0 + ch);
        }
        cp_commit();
    };

#pragma unroll
    for (int s = 0; s < STAGES; ++s) issue(s, s);

    int buf = 0;
    for (int i = 0; i < NCHUNK; ++i) {
        cp_wait3();
        __syncthreads();

        const uint32_t* A0 = (const uint32_t*)(As + buf * A_TILE + (wm * 64) * BKP);
        const uint32_t* B0 = (const uint32_t*)(Bs + buf * B_TILE + (wn * 32) * BKP);

#pragma unroll
        for (int ks = 0; ks < 4; ++ks) {
            const int kk = ks * 8;
            uint32_t a[4][4], b[4][2];
#pragma unroll
            for (int mf = 0; mf < 4; ++mf) {
                const uint32_t* ap = A0 + (mf * 16 + g) * BKP + kk + tg;
                a[mf][0] = ap[0];
                a[mf][1] = ap[8 * BKP];
                a[mf][2] = ap[4];
                a[mf][3] = ap[8 * BKP + 4];
            }
#pragma unroll
            for (int nf = 0; nf < 4; ++nf) {
                const uint32_t* bp = B0 + (nf * 8 + g) * BKP + kk + tg;
                b[nf][0] = bp[0];
                b[nf][1] = bp[4];
            }
#pragma unroll
            for (int mf = 0; mf < 4; ++mf)
#pragma unroll
                for (int nf = 0; nf < 4; ++nf)
                    mma_tf32(acc[mf][nf], a[mf], b[nf]);
        }

        __syncthreads();
        if (i + STAGES < NCHUNK) issue(i + STAGES, buf);
        buf = (buf == STAGES - 1) ? 0 : buf + 1;
    }

    // ---- epilogue ----
#pragma unroll
    for (int mf = 0; mf < 4; ++mf) {
#pragma unroll
        for (int nf = 0; nf < 4; ++nf) {
            const int n = bn + wn * 32 + nf * 8 + 2 * tg;
            const float2 bi = *(const float2*)(bias + n);
#pragma unroll
            for (int half = 0; half < 2; ++half) {
                const int m = bm + wm * 64 + mf * 16 + g + half * 8;
                const size_t idx = (size_t)m * HID + n;
                float v0 = acc[mf][nf][2 * half + 0] + bi.x;
                float v1 = acc[mf][nf][2 * half + 1] + bi.y;
                float2 o;
                if (mode == 0) {
                    const float2 hp = *(const float2*)(hprev + idx);
                    o.x = __uint_as_float(f2tf32(fsigmoid(v0) * hp.x));
                    o.y = __uint_as_float(f2tf32(fsigmoid(v1) * hp.y));
                } else if (mode == 1) {
                    o.x = fsigmoid(v0);
                    o.y = fsigmoid(v1);
                } else {
                    const float2 hp = *(const float2*)(hprev + idx);
                    const float2 zz = *(const float2*)(zbuf + idx);
                    o.x = fmaf(zz.x, ftanh(v0) - hp.x, hp.x);
                    o.y = fmaf(zz.y, ftanh(v1) - hp.y, hp.y);
                }
                *(float2*)(out + idx) = o;
            }
        }
    }
}

static inline void round_pass(const float* src, float* dst, size_t n) {
    const int n4 = (int)(n / 4);
    const int blocks = (n4 + 256 * 8 - 1) / (256 * 8);
    round_tf32_kernel<<<blocks, 256>>>((const float4*)src, (float4*)dst, n4);
}

extern "C" void kernel_launch(void* const* d_in, const int* in_sizes, int n_in,
                              void* d_out, int out_size)
{
    const float* x     = (const float*)d_in[0];
    const float* hprev = (const float*)d_in[1];
    const float* c     = (const float*)d_in[2];
    const float* Wh    = (const float*)d_in[3];
    const float* Wz    = (const float*)d_in[4];
    const float* Wr    = (const float*)d_in[5];
    const float* Uh    = (const float*)d_in[6];
    const float* Uz    = (const float*)d_in[7];
    const float* Ur    = (const float*)d_in[8];
    const float* Ch    = (const float*)d_in[9];
    const float* Cz    = (const float*)d_in[10];
    const float* Cr    = (const float*)d_in[11];
    const float* bh    = (const float*)d_in[12];
    const float* bz    = (const float*)d_in[13];
    const float* br    = (const float*)d_in[14];
    float* out = (float*)d_out;

    float *rh_p, *z_p, *xr_p, *hr_p, *cr_p, *wts_p;
    cudaGetSymbolAddress((void**)&rh_p,  g_rh);
    cudaGetSymbolAddress((void**)&z_p,   g_z);
    cudaGetSymbolAddress((void**)&xr_p,  g_xr);
    cudaGetSymbolAddress((void**)&hr_p,  g_hr);
    cudaGetSymbolAddress((void**)&cr_p,  g_cr);
    cudaGetSymbolAddress((void**)&wts_p, g_wts);

    const size_t M1 = (size_t)1024 * 1024;
    // gate weight slots: [gate*4M + 0: W][+1M: U][+2M: C(2M)]
    float* wr_W = wts_p + 0 * 4 * M1; float* wr_U = wr_W + M1; float* wr_C = wr_U + M1;
    float* wz_W = wts_p + 1 * 4 * M1; float* wz_U = wz_W + M1; float* wz_C = wz_U + M1;
    float* wh_W = wts_p + 2 * 4 * M1; float* wh_U = wh_W + M1; float* wh_C = wh_U + M1;

    // ---- pre-round everything to tf32 ----
    round_pass(x,     xr_p, (size_t)BATCH * 1024);
    round_pass(hprev, hr_p, (size_t)BATCH * 1024);
    round_pass(c,     cr_p, (size_t)BATCH * 2048);
    round_pass(Wr, wr_W, M1);  round_pass(Ur, wr_U, M1);  round_pass(Cr, wr_C, 2 * M1);
    round_pass(Wz, wz_W, M1);  round_pass(Uz, wz_U, M1);  round_pass(Cz, wz_C, 2 * M1);
    round_pass(Wh, wh_W, M1);  round_pass(Uh, wh_U, M1);  round_pass(Ch, wh_C, 2 * M1);

    cudaFuncSetAttribute(gate_mma_kernel,
                         cudaFuncAttributeMaxDynamicSharedMemorySize, SMEM_BYTES);

    const dim3 grid(HID / BN, BATCH / BM);  // (8, 32)
    const dim3 block(512);

    // r gate -> g_rh = tf32(sigmoid(.) * hprev)
    gate_mma_kernel<<<grid, block, SMEM_BYTES>>>(
        xr_p, hr_p, cr_p, wr_W, wr_U, wr_C, br, hprev, nullptr, rh_p, 0);
    // z gate -> g_z
    gate_mma_kernel<<<grid, block, SMEM_BYTES>>>(
        xr_p, hr_p, cr_p, wz_W, wz_U, wz_C, bz, hprev, nullptr, z_p, 1);
    // h gate -> out
    gate_mma_kernel<<<grid, block, SMEM_BYTES>>>(
        xr_p, rh_p, cr_p, wh_W, wh_U, wh_C, bh, hprev, z_p, out, 2);
}

// round 5
// speedup vs baseline: 3.6839x; 1.0605x over previous
#include <cuda_runtime.h>
#include <cstdint>
#include <math.h>

// GRU-style decoder cell via mma.sync tf32; float4 fragment loads + swizzled smem.
//   r = sigmoid(x@Wr^T + hprev@Ur^T + c@Cr^T + br)   -> g_rh = tf32(r*hprev)
//   z = sigmoid(x@Wz^T + hprev@Uz^T + c@Cz^T + bz)   -> g_z
//   h = tanh   (x@Wh^T + g_rh@Uh^T  + c@Ch^T + bh)   -> out = z*h + (1-z)*hprev
// B=8192, IN=1024, H=1024, c:[B,2048]; effective K=4096 per gate.

#define BATCH 8192
#define HID   1024
#define BM 256
#define BN 128
#define BK 32            // floats per chunk; 8 16B-chunks per row
#define STAGES 4
#define NCHUNK 128       // 4096 / 32

#define A_TILE (BM * BK)            // floats (8192)
#define B_TILE (BN * BK)            // floats (4096)
#define SMEM_BYTES ((STAGES * (A_TILE + B_TILE)) * 4)  // 196608

// ---- scratch ----
__device__ float g_rh[(size_t)BATCH * HID];
__device__ float g_z [(size_t)BATCH * HID];
__device__ float g_xr[(size_t)BATCH * 1024];
__device__ float g_hr[(size_t)BATCH * 1024];
__device__ float g_cr[(size_t)BATCH * 2048];
__device__ float g_wts[(size_t)3 * 4 * 1024 * 1024];

__device__ __forceinline__ void cp16(void* dst_smem, const void* src) {
    uint32_t d = (uint32_t)__cvta_generic_to_shared(dst_smem);
    asm volatile("cp.async.cg.shared.global [%0], [%1], 16;" :: "r"(d), "l"(src));
}
__device__ __forceinline__ void cp_commit() {
    asm volatile("cp.async.commit_group;" ::: "memory");
}
__device__ __forceinline__ void cp_wait2() {
    asm volatile("cp.async.wait_group 2;" ::: "memory");
}
__device__ __forceinline__ uint32_t f2tf32(float x) {
    uint32_t u;
    asm("cvt.rna.tf32.f32 %0, %1;" : "=r"(u) : "f"(x));
    return u;
}
__device__ __forceinline__ void mma_tf32(float* c, uint32_t a0, uint32_t a1,
                                         uint32_t a2, uint32_t a3,
                                         uint32_t b0, uint32_t b1) {
    asm volatile(
        "mma.sync.aligned.m16n8k8.row.col.f32.tf32.tf32.f32 "
        "{%0,%1,%2,%3}, {%4,%5,%6,%7}, {%8,%9}, {%0,%1,%2,%3};"
        : "+f"(c[0]), "+f"(c[1]), "+f"(c[2]), "+f"(c[3])
        : "r"(a0), "r"(a1), "r"(a2), "r"(a3), "r"(b0), "r"(b1));
}
__device__ __forceinline__ float fsigmoid(float v) { return 1.0f / (1.0f + __expf(-v)); }
__device__ __forceinline__ float ftanh(float v) {
    float e = __expf(-2.0f * v);
    return 2.0f / (1.0f + e) - 1.0f;
}

// ---- pre-pass: tf32 rounding ----
__global__ __launch_bounds__(256)
void round_tf32_kernel(const float4* __restrict__ src, float4* __restrict__ dst, int n4)
{
    const int stride = gridDim.x * blockDim.x;
    for (int i = blockIdx.x * blockDim.x + threadIdx.x; i < n4; i += stride) {
        float4 v = src[i];
        v.x = __uint_as_float(f2tf32(v.x));
        v.y = __uint_as_float(f2tf32(v.y));
        v.z = __uint_as_float(f2tf32(v.z));
        v.w = __uint_as_float(f2tf32(v.w));
        dst[i] = v;
    }
}

__global__ __launch_bounds__(512, 1)
void gate_mma_kernel(
    const float* __restrict__ x,
    const float* __restrict__ A1,
    const float* __restrict__ c,
    const float* __restrict__ W0,
    const float* __restrict__ W1,
    const float* __restrict__ W2,
    const float* __restrict__ bias,
    const float* __restrict__ hprev,
    const float* __restrict__ zbuf,
    float* __restrict__ out,
    int mode)
{
    extern __shared__ float sm[];
    float* As = sm;                      // [STAGES][BM][32] swizzled
    float* Bs = sm + STAGES * A_TILE;    // [STAGES][BN][32] swizzled

    const int tid  = threadIdx.x;
    const int lane = tid & 31;
    const int wid  = tid >> 5;
    const int g    = lane >> 2;   // 0..7
    const int tg   = lane & 3;    // 0..3
    const int wm   = wid >> 2;    // 0..3 -> 64-row slab
    const int wn   = wid & 3;     // 0..3 -> 32-col slab

    const int bm = blockIdx.y * BM;
    const int bn = blockIdx.x * BN;

    // lane-constant swizzled read offsets (floats) per k16-window w:
    //   loff[w] = g*32 + (((w ^ (g&1)) << 2) + tg) * 4
    const int sw  = g & 1;
    const int loff0 = g * 32 + ((((0 ^ sw) << 2) + tg) << 2);
    const int loff1 = g * 32 + ((((1 ^ sw) << 2) + tg) << 2);

    float acc[4][4][4];
#pragma unroll
    for (int i = 0; i < 4; ++i)
#pragma unroll
        for (int j = 0; j < 4; ++j)
#pragma unroll
            for (int k = 0; k < 4; ++k)
                acc[i][j][k] = 0.0f;

    auto issue = [&](int i) {
        const int s = i & 3;
        const float* Aseg;
        const float* Wseg;
        int ld, k0;
        if (i < 32)      { Aseg = x;  Wseg = W0; ld = 1024; k0 = i * BK; }
        else if (i < 64) { Aseg = A1; Wseg = W1; ld = 1024; k0 = (i - 32) * BK; }
        else             { Aseg = c;  Wseg = W2; ld = 2048; k0 = (i - 64) * BK; }

        float* ad = As + s * A_TILE;
        float* bd = Bs + s * B_TILE;
        // A: 256 rows x 8 chunks = 2048 cp16; 512 threads -> 4 each
#pragma unroll
        for (int j = 0; j < 4; ++j) {
            const int idx = tid + j * 512;
            const int row = idx >> 3;
            const int ch  = idx & 7;
            const int swc = ch ^ ((row & 1) << 2);
            cp16(ad + row * 32 + (swc << 2),
                 Aseg + (size_t)(bm + row) * ld + k0 + (ch << 2));
        }
        // B: 128 rows x 8 chunks = 1024; 512 threads -> 2 each
#pragma unroll
        for (int j = 0; j < 2; ++j) {
            const int idx = tid + j * 512;
            const int row = idx >> 3;
            const int ch  = idx & 7;
            const int swc = ch ^ ((row & 1) << 2);
            cp16(bd + row * 32 + (swc << 2),
                 Wseg + (size_t)(bn + row) * ld + k0 + (ch << 2));
        }
        cp_commit();
    };

    issue(0); issue(1); issue(2);

    for (int i = 0; i < NCHUNK; ++i) {
        cp_wait2();
        __syncthreads();
        if (i + 3 < NCHUNK) issue(i + 3);   // writes stage (i-1)&3: readers done

        const int buf = i & 3;
        const float* A0 = As + buf * A_TILE + (wm * 64) * 32;
        const float* B0 = Bs + buf * B_TILE + (wn * 32) * 32;

#pragma unroll
        for (int w = 0; w < 2; ++w) {
            const int lo = (w == 0) ? loff0 : loff1;
            // B frags: one float4 per nf feeds both MMAs of this window
            float4 bv[4];
#pragma unroll
            for (int nf = 0; nf < 4; ++nf)
                bv[nf] = *(const float4*)(B0 + nf * 256 + lo);
#pragma unroll
            for (int mf = 0; mf < 4; ++mf) {
                const float4 a0v = *(const float4*)(A0 + mf * 512 + lo);
                const float4 a1v = *(const float4*)(A0 + mf * 512 + 256 + lo);
#pragma unroll
                for (int nf = 0; nf < 4; ++nf) {
                    // MMA1: lane tg owns k=4tg, 4tg+1
                    mma_tf32(acc[mf][nf],
                             __float_as_uint(a0v.x), __float_as_uint(a1v.x),
                             __float_as_uint(a0v.y), __float_as_uint(a1v.y),
                             __float_as_uint(bv[nf].x), __float_as_uint(bv[nf].y));
                    // MMA2: lane tg owns k=4tg+2, 4tg+3
                    mma_tf32(acc[mf][nf],
                             __float_as_uint(a0v.z), __float_as_uint(a1v.z),
                             __float_as_uint(a0v.w), __float_as_uint(a1v.w),
                             __float_as_uint(bv[nf].z), __float_as_uint(bv[nf].w));
                }
            }
        }
    }

    // ---- epilogue ----
#pragma unroll
    for (int mf = 0; mf < 4; ++mf) {
#pragma unroll
        for (int nf = 0; nf < 4; ++nf) {
            const int n = bn + wn * 32 + nf * 8 + 2 * tg;
            const float2 bi = *(const float2*)(bias + n);
#pragma unroll
            for (int half = 0; half < 2; ++half) {
                const int m = bm + wm * 64 + mf * 16 + g + half * 8;
                const size_t idx = (size_t)m * HID + n;
                float v0 = acc[mf][nf][2 * half + 0] + bi.x;
                float v1 = acc[mf][nf][2 * half + 1] + bi.y;
                float2 o;
                if (mode == 0) {
                    const float2 hp = *(const float2*)(hprev + idx);
                    o.x = __uint_as_float(f2tf32(fsigmoid(v0) * hp.x));
                    o.y = __uint_as_float(f2tf32(fsigmoid(v1) * hp.y));
                } else if (mode == 1) {
                    o.x = fsigmoid(v0);
                    o.y = fsigmoid(v1);
                } else {
                    const float2 hp = *(const float2*)(hprev + idx);
                    const float2 zz = *(const float2*)(zbuf + idx);
                    o.x = fmaf(zz.x, ftanh(v0) - hp.x, hp.x);
                    o.y = fmaf(zz.y, ftanh(v1) - hp.y, hp.y);
                }
                *(float2*)(out + idx) = o;
            }
        }
    }
}

static inline void round_pass(const float* src, float* dst, size_t n) {
    const int n4 = (int)(n / 4);
    int blocks = (n4 + 256 * 2 - 1) / (256 * 2);
    if (blocks > 4096) blocks = 4096;
    round_tf32_kernel<<<blocks, 256>>>((const float4*)src, (float4*)dst, n4);
}

extern "C" void kernel_launch(void* const* d_in, const int* in_sizes, int n_in,
                              void* d_out, int out_size)
{
    const float* x     = (const float*)d_in[0];
    const float* hprev = (const float*)d_in[1];
    const float* c     = (const float*)d_in[2];
    const float* Wh    = (const float*)d_in[3];
    const float* Wz    = (const float*)d_in[4];
    const float* Wr    = (const float*)d_in[5];
    const float* Uh    = (const float*)d_in[6];
    const float* Uz    = (const float*)d_in[7];
    const float* Ur    = (const float*)d_in[8];
    const float* Ch    = (const float*)d_in[9];
    const float* Cz    = (const float*)d_in[10];
    const float* Cr    = (const float*)d_in[11];
    const float* bh    = (const float*)d_in[12];
    const float* bz    = (const float*)d_in[13];
    const float* br    = (const float*)d_in[14];
    float* out = (float*)d_out;

    float *rh_p, *z_p, *xr_p, *hr_p, *cr_p, *wts_p;
    cudaGetSymbolAddress((void**)&rh_p,  g_rh);
    cudaGetSymbolAddress((void**)&z_p,   g_z);
    cudaGetSymbolAddress((void**)&xr_p,  g_xr);
    cudaGetSymbolAddress((void**)&hr_p,  g_hr);
    cudaGetSymbolAddress((void**)&cr_p,  g_cr);
    cudaGetSymbolAddress((void**)&wts_p, g_wts);

    const size_t M1 = (size_t)1024 * 1024;
    float* wr_W = wts_p + 0 * 4 * M1; float* wr_U = wr_W + M1; float* wr_C = wr_U + M1;
    float* wz_W = wts_p + 1 * 4 * M1; float* wz_U = wz_W + M1; float* wz_C = wz_U + M1;
    float* wh_W = wts_p + 2 * 4 * M1; float* wh_U = wh_W + M1; float* wh_C = wh_U + M1;

    round_pass(x,     xr_p, (size_t)BATCH * 1024);
    round_pass(hprev, hr_p, (size_t)BATCH * 1024);
    round_pass(c,     cr_p, (size_t)BATCH * 2048);
    round_pass(Wr, wr_W, M1);  round_pass(Ur, wr_U, M1);  round_pass(Cr, wr_C, 2 * M1);
    round_pass(Wz, wz_W, M1);  round_pass(Uz, wz_U, M1);  round_pass(Cz, wz_C, 2 * M1);
    round_pass(Wh, wh_W, M1);  round_pass(Uh, wh_U, M1);  round_pass(Ch, wh_C, 2 * M1);

    cudaFuncSetAttribute(gate_mma_kernel,
                         cudaFuncAttributeMaxDynamicSharedMemorySize, SMEM_BYTES);

    const dim3 grid(HID / BN, BATCH / BM);  // (8, 32)
    const dim3 block(512);

    gate_mma_kernel<<<grid, block, SMEM_BYTES>>>(
        xr_p, hr_p, cr_p, wr_W, wr_U, wr_C, br, hprev, nullptr, rh_p, 0);
    gate_mma_kernel<<<grid, block, SMEM_BYTES>>>(
        xr_p, hr_p, cr_p, wz_W, wz_U, wz_C, bz, hprev, nullptr, z_p, 1);
    gate_mma_kernel<<<grid, block, SMEM_BYTES>>>(
        xr_p, rh_p, cr_p, wh_W, wh_U, wh_C, bh, hprev, z_p, out, 2);
}